// round 7
// baseline (speedup 1.0000x reference)
#include <cuda_runtime.h>

// ---------------- configuration ----------------
#define T        256
#define NTHREADS 512
#define MAXN     2097152

#define S 264    // row stride (floats) for ALL activation arrays

// smem float offsets
#define OW1   0        // 100   w1T[t*20+co]
#define OB1   100      // 20
#define OW2   120      // 4000  w2T[(ci*5+t)*40+co]
#define OB2   4120     // 40
#define OW3   4160     // 3200  w3T[ci*80+co]
#define OB3   7360     // 80
#define OW4   7440     // 3200  w4T[ci*40+co]
#define OB4   10640    // 40
#define OW5   10680    // 2400  w5T[(ci*3+t)*20+co]
#define OB5   13080    // 20
#define OW6   13100    // 20
#define OB6   13120    // 1
#define ODIF  13124    // 268 (266 real)
#define OY13  13392    // y1 (20*264=5280) then y3 (80*264=21120)
#define OY24  34512    // y2 (40*264=10560) then y4
#define OY5   45072    // y5 (20*264=5280)
#define SMEM_FLOATS 50352
#define SMEM_BYTES  (SMEM_FLOATS * 4)

__device__ float g_bm[MAXN];

typedef unsigned long long u64;

// ---------------- f32x2 helpers (sm_100+ packed fp32) ----------------
__device__ __forceinline__ u64 splat2(float a) {
    u64 r; asm("mov.b64 %0, {%1, %1};" : "=l"(r) : "f"(a)); return r;
}
__device__ __forceinline__ u64 fma2(u64 a, u64 b, u64 c) {
    u64 d; asm("fma.rn.f32x2 %0, %1, %2, %3;" : "=l"(d) : "l"(a), "l"(b), "l"(c)); return d;
}
__device__ __forceinline__ void unpk(u64 v, float& x, float& y) {
    asm("mov.b64 {%0, %1}, %2;" : "=f"(x), "=f"(y) : "l"(v));
}

__device__ __forceinline__ float elu1(float x) {
    float e = __expf(x) - 1.0f;
    return x > 0.0f ? x : e;
}

__global__ __launch_bounds__(NTHREADS)
void cnn_kernel(const float* __restrict__ uu,
                const float* __restrict__ w1, const float* __restrict__ b1,
                const float* __restrict__ w2, const float* __restrict__ b2,
                const float* __restrict__ w3, const float* __restrict__ b3,
                const float* __restrict__ w4, const float* __restrict__ b4,
                const float* __restrict__ w5, const float* __restrict__ b5,
                const float* __restrict__ w6, const float* __restrict__ b6,
                int N)
{
    extern __shared__ float s[];
    const int tid = threadIdx.x;
    const int g0  = blockIdx.x * T;

    // ---- load + transpose weights ----
    for (int i = tid; i < 100; i += NTHREADS) {           // w1 (20,1,5)
        int co = i / 5, t = i % 5;
        s[OW1 + t * 20 + co] = w1[i];
    }
    for (int i = tid; i < 20; i += NTHREADS)  s[OB1 + i] = b1[i];
    for (int i = tid; i < 4000; i += NTHREADS) {          // w2 (40,20,5)
        int co = i / 100, r = i % 100, ci = r / 5, t = r % 5;
        s[OW2 + (ci * 5 + t) * 40 + co] = w2[i];
    }
    for (int i = tid; i < 40; i += NTHREADS)  s[OB2 + i] = b2[i];
    for (int i = tid; i < 3200; i += NTHREADS) {          // w3 (80,40,1)
        int co = i / 40, ci = i % 40;
        s[OW3 + ci * 80 + co] = w3[i];
    }
    for (int i = tid; i < 80; i += NTHREADS)  s[OB3 + i] = b3[i];
    for (int i = tid; i < 3200; i += NTHREADS) {          // w4 (40,80,1)
        int co = i / 80, ci = i % 80;
        s[OW4 + ci * 40 + co] = w4[i];
    }
    for (int i = tid; i < 40; i += NTHREADS)  s[OB4 + i] = b4[i];
    for (int i = tid; i < 2400; i += NTHREADS) {          // w5 (20,40,3)
        int co = i / 120, r = i % 120, ci = r / 3, t = r % 3;
        s[OW5 + (ci * 3 + t) * 20 + co] = w5[i];
    }
    for (int i = tid; i < 20; i += NTHREADS)  s[OB5 + i] = b5[i];
    for (int i = tid; i < 20; i += NTHREADS)  s[OW6 + i] = w6[i];
    if (tid == 0) s[OB6] = b6[0];

    // ---- dif = avg_diff(uu), local window [g0-5, g0+261), real ld<266 ----
    for (int ld = tid; ld < 268; ld += NTHREADS) {
        int gd = g0 - 5 + ld;
        float v = 0.0f;
        if (ld < 266 && gd >= 0 && gd < N) {
            if (gd == 0)            v = __ldg(&uu[1]) - __ldg(&uu[0]);
            else if (gd == N - 1)   v = __ldg(&uu[N - 1]) - __ldg(&uu[N - 2]);
            else                    v = 0.5f * (__ldg(&uu[gd + 1]) - __ldg(&uu[gd - 1]));
        }
        s[ODIF + ld] = v;
    }
    __syncthreads();

    // ---- layer 1: 1 -> 20, k=5, pad 2. y1[lp] at gp = g0-3+lp, real lp<262 ----
    for (int item = tid; item < 20 * 264; item += NTHREADS) {
        int co = item / 264, lp = item % 264;
        float acc = s[OB1 + co];
        #pragma unroll
        for (int t = 0; t < 5; t++)
            acc += s[OW1 + t * 20 + co] * s[ODIF + lp + t];
        int gp = g0 - 3 + lp;
        float v = elu1(acc);
        if (lp >= 262 || gp < 0 || gp >= N) v = 0.0f;
        s[OY13 + co * S + lp] = v;
    }
    __syncthreads();

    // ---- layer 2: 20 -> 40, k=5, pad 2. y2[lp] at gp = g0-1+lp, real lp<258 ----
    // 480 items: 20 ch-pairs x 24 posgroups (P_T=11, covers 264)
    if (tid < 480) {
        const int cog = tid / 24, posg = tid % 24;
        const int co0 = cog * 2, lp0 = posg * 11;
        u64 acc[11];
        {
            u64 bp = *reinterpret_cast<const u64*>(&s[OB2 + co0]);
            #pragma unroll
            for (int p = 0; p < 11; p++) acc[p] = bp;
        }
        for (int ci = 0; ci < 20; ci++) {
            const float* yr = &s[OY13 + ci * S + lp0];
            const float* wp = &s[OW2 + ci * 5 * 40 + co0];
            u64 as[15];
            #pragma unroll
            for (int j = 0; j < 15; j++) as[j] = splat2(yr[j]);
            #pragma unroll
            for (int t = 0; t < 5; t++) {
                u64 w = *reinterpret_cast<const u64*>(&wp[t * 40]);
                #pragma unroll
                for (int p = 0; p < 11; p++)
                    acc[p] = fma2(w, as[t + p], acc[p]);
            }
        }
        #pragma unroll
        for (int p = 0; p < 11; p++) {
            int lp = lp0 + p, gp = g0 - 1 + lp;
            bool kill = (lp >= 258) | (gp < 0) | (gp >= N);
            float x, y; unpk(acc[p], x, y);
            float v0 = elu1(x), v1 = elu1(y);
            if (kill) { v0 = 0.0f; v1 = 0.0f; }
            if (lp < S) {
                s[OY24 + co0 * S + lp] = v0;
                s[OY24 + (co0 + 1) * S + lp] = v1;
            }
        }
    }
    __syncthreads();

    // ---- layer 3: 40 -> 80, k=1. 430 items: 5 cog (8 ch-pairs) x 86 posg (P_T=3) ----
    if (tid < 430) {
        const int cog = tid / 86, posg = tid % 86;
        const int co0 = cog * 16, lp0 = posg * 3;
        u64 acc[8][3];
        #pragma unroll
        for (int c = 0; c < 8; c++) {
            u64 bp = *reinterpret_cast<const u64*>(&s[OB3 + co0 + 2 * c]);
            acc[c][0] = bp; acc[c][1] = bp; acc[c][2] = bp;
        }
        for (int ci = 0; ci < 40; ci++) {
            const float* yr = &s[OY24 + ci * S + lp0];
            u64 a0 = splat2(yr[0]), a1 = splat2(yr[1]), a2 = splat2(yr[2]);
            const u64* wp = reinterpret_cast<const u64*>(&s[OW3 + ci * 80 + co0]);
            #pragma unroll
            for (int c = 0; c < 8; c++) {
                u64 w = wp[c];
                acc[c][0] = fma2(w, a0, acc[c][0]);
                acc[c][1] = fma2(w, a1, acc[c][1]);
                acc[c][2] = fma2(w, a2, acc[c][2]);
            }
        }
        #pragma unroll
        for (int c = 0; c < 8; c++)
            #pragma unroll
            for (int p = 0; p < 3; p++) {
                int lp = lp0 + p, gp = g0 - 1 + lp;
                bool kill = (lp >= 258) | (gp < 0) | (gp >= N);
                float x, y; unpk(acc[c][p], x, y);
                float v0 = elu1(x), v1 = elu1(y);
                if (kill) { v0 = 0.0f; v1 = 0.0f; }
                s[OY13 + (co0 + 2 * c) * S + lp] = v0;
                s[OY13 + (co0 + 2 * c + 1) * S + lp] = v1;
            }
    }
    __syncthreads();

    // ---- layer 4: 80 -> 40, k=1. 430 items: 5 cog (4 ch-pairs) x 86 posg (P_T=3) ----
    if (tid < 430) {
        const int cog = tid / 86, posg = tid % 86;
        const int co0 = cog * 8, lp0 = posg * 3;
        u64 acc[4][3];
        #pragma unroll
        for (int c = 0; c < 4; c++) {
            u64 bp = *reinterpret_cast<const u64*>(&s[OB4 + co0 + 2 * c]);
            acc[c][0] = bp; acc[c][1] = bp; acc[c][2] = bp;
        }
        for (int ci = 0; ci < 80; ci++) {
            const float* yr = &s[OY13 + ci * S + lp0];
            u64 a0 = splat2(yr[0]), a1 = splat2(yr[1]), a2 = splat2(yr[2]);
            const u64* wp = reinterpret_cast<const u64*>(&s[OW4 + ci * 40 + co0]);
            #pragma unroll
            for (int c = 0; c < 4; c++) {
                u64 w = wp[c];
                acc[c][0] = fma2(w, a0, acc[c][0]);
                acc[c][1] = fma2(w, a1, acc[c][1]);
                acc[c][2] = fma2(w, a2, acc[c][2]);
            }
        }
        #pragma unroll
        for (int c = 0; c < 4; c++)
            #pragma unroll
            for (int p = 0; p < 3; p++) {
                int lp = lp0 + p, gp = g0 - 1 + lp;
                bool kill = (lp >= 258) | (gp < 0) | (gp >= N);
                float x, y; unpk(acc[c][p], x, y);
                float v0 = elu1(x), v1 = elu1(y);
                if (kill) { v0 = 0.0f; v1 = 0.0f; }
                s[OY24 + (co0 + 2 * c) * S + lp] = v0;
                s[OY24 + (co0 + 2 * c + 1) * S + lp] = v1;
            }
    }
    __syncthreads();

    // ---- layer 5: 40 -> 20, k=3, pad 1. y5[lp] at gp = g0+lp, real lp<256 ----
    // 430 items: 10 cog (1 ch-pair) x 43 posg (P_T=6, covers 258)
    if (tid < 430) {
        const int cog = tid / 43, posg = tid % 43;
        const int co0 = cog * 2, lp0 = posg * 6;
        u64 acc[6];
        {
            u64 bp = *reinterpret_cast<const u64*>(&s[OB5 + co0]);
            #pragma unroll
            for (int p = 0; p < 6; p++) acc[p] = bp;
        }
        for (int ci = 0; ci < 40; ci++) {
            const float* yr = &s[OY24 + ci * S + lp0];
            const float* wp = &s[OW5 + ci * 3 * 20 + co0];
            u64 as[8];
            #pragma unroll
            for (int j = 0; j < 8; j++) as[j] = splat2(yr[j]);
            #pragma unroll
            for (int t = 0; t < 3; t++) {
                u64 w = *reinterpret_cast<const u64*>(&wp[t * 20]);
                #pragma unroll
                for (int p = 0; p < 6; p++)
                    acc[p] = fma2(w, as[t + p], acc[p]);
            }
        }
        #pragma unroll
        for (int p = 0; p < 6; p++) {
            int lp = lp0 + p, gp = g0 + lp;
            bool kill = (lp >= 256) | (gp >= N);
            float x, y; unpk(acc[p], x, y);
            float v0 = elu1(x), v1 = elu1(y);
            if (kill) { v0 = 0.0f; v1 = 0.0f; }
            s[OY5 + co0 * S + lp] = v0;
            s[OY5 + (co0 + 1) * S + lp] = v1;
        }
    }
    __syncthreads();

    // ---- layer 6: 20 -> 1, k=1, sigmoid, + 0.1 ----
    for (int lp = tid; lp < T; lp += NTHREADS) {
        int gp = g0 + lp;
        if (gp < N) {
            float acc = s[OB6];
            #pragma unroll
            for (int c = 0; c < 20; c++)
                acc += s[OW6 + c] * s[OY5 + c * S + lp];
            float sg = 1.0f / (1.0f + __expf(-acc));
            g_bm[gp] = sg + 0.1f;
        }
    }
}

// ---------------- WENO reconstruction ----------------
__device__ __forceinline__ float weno_flux(float a, float b, float c, float d, float e,
                                           float bm_m1, float bm_0, float bm_p1)
{
    const float C1312 = 13.0f / 12.0f;
    const float E = 1e-13f;
    float f0 = (11.0f * c - 7.0f * d + 2.0f * e) * (1.0f / 6.0f);
    float f1 = (2.0f * b + 5.0f * c - d) * (1.0f / 6.0f);
    float f2 = (-a + 5.0f * b + 2.0f * c) * (1.0f / 6.0f);

    float t0a = c - 2.0f * d + e, t0b = 3.0f * c - 4.0f * d + e;
    float t1a = b - 2.0f * c + d, t1b = b - d;
    float t2a = a - 2.0f * b + c, t2b = a - 4.0f * b + 3.0f * c;
    float b0 = C1312 * t0a * t0a + 0.25f * t0b * t0b;
    float b1 = C1312 * t1a * t1a + 0.25f * t1b * t1b;
    float b2 = C1312 * t2a * t2a + 0.25f * t2b * t2b;

    b0 *= bm_p1;
    b1 *= bm_0;
    b2 *= bm_m1;

    float brs = (b2 - b0) * (b2 - b0);
    float e0 = (E + b0) * (E + b0);
    float e1 = (E + b1) * (E + b1);
    float e2 = (E + b2) * (E + b2);
    float om0 = 0.1f / e0 * (brs + e0);
    float om1 = 0.6f / e1 * (brs + e1);
    float om2 = 0.3f / e2 * (brs + e2);
    return (om0 * f0 + om1 * f1 + om2 * f2) / (om0 + om1 + om2);
}

__global__ void weno_kernel(const float* __restrict__ uu, float* __restrict__ out, int N)
{
    int i = blockIdx.x * blockDim.x + threadIdx.x;
    if (i >= N) return;
    int im2 = i - 2, im1 = i - 1, ip1 = i + 1, ip2 = i + 2, ip3 = i + 3;
    if (im2 < 0) im2 += N;
    if (im1 < 0) im1 += N;
    if (ip1 >= N) ip1 -= N;
    if (ip2 >= N) ip2 -= N;
    if (ip3 >= N) ip3 -= N;

    float umm = __ldg(&uu[im2]), um = __ldg(&uu[im1]), u0 = __ldg(&uu[i]);
    float up  = __ldg(&uu[ip1]), upp = __ldg(&uu[ip2]), uppp = __ldg(&uu[ip3]);
    float bm_m1 = g_bm[im1], bm_0 = g_bm[i], bm_p1 = g_bm[ip1];

    float fluxp = weno_flux(um, u0, up, upp, uppp, bm_m1, bm_0, bm_p1);
    float fluxn = weno_flux(umm, um, u0, up, upp, bm_m1, bm_0, bm_p1);

    out[i] = fluxp - fluxn;
}

extern "C" void kernel_launch(void* const* d_in, const int* in_sizes, int n_in,
                              void* d_out, int out_size)
{
    const float* uu = (const float*)d_in[0];
    const float* w1 = (const float*)d_in[1];
    const float* b1 = (const float*)d_in[2];
    const float* w2 = (const float*)d_in[3];
    const float* b2 = (const float*)d_in[4];
    const float* w3 = (const float*)d_in[5];
    const float* b3 = (const float*)d_in[6];
    const float* w4 = (const float*)d_in[7];
    const float* b4 = (const float*)d_in[8];
    const float* w5 = (const float*)d_in[9];
    const float* b5 = (const float*)d_in[10];
    const float* w6 = (const float*)d_in[11];
    const float* b6 = (const float*)d_in[12];
    float* out = (float*)d_out;
    int N = in_sizes[0];

    cudaFuncSetAttribute(cnn_kernel, cudaFuncAttributeMaxDynamicSharedMemorySize, SMEM_BYTES);

    int nb = (N + T - 1) / T;
    cnn_kernel<<<nb, NTHREADS, SMEM_BYTES>>>(uu, w1, b1, w2, b2, w3, b3, w4, b4,
                                             w5, b5, w6, b6, N);
    weno_kernel<<<(N + 255) / 256, 256>>>(uu, out, N);
}

// round 8
// speedup vs baseline: 1.4767x; 1.4767x over previous
#include <cuda_runtime.h>

// ---------------- configuration ----------------
#define T        100
#define NTHREADS 256
#define MAXN     2097152

#define S1 112   // y1 / y5 row stride
#define S2 108   // y2 / y3 / y4 row stride

// smem float offsets (all u64-load bases even)
#define OW1   0        // 100   w1T[t*20+co]
#define OB1   100      // 20
#define OW2   120      // 4000  w2T[(ci*5+t)*40+co]
#define OB2   4120     // 40
#define OW3   4160     // 3200  w3T[ci*80+co]
#define OB3   7360     // 80
#define OW4   7440     // 3200  w4T[ci*40+co]
#define OB4   10640    // 40
#define OW5   10680    // 2400  w5T[(ci*3+t)*20+co]
#define OB5   13080    // 20
#define OW6   13100    // 20
#define OB6   13120    // 1
#define ODIF  13122    // 118 floats (110 real, rest zero)
#define OY1   13240    // y1: 20*112 = 2240   (later reused for y5)
#define OY2   15480    // y2: 40*108 = 4320   (later reused for y4)
#define OY3   19800    // y3: 80*108 = 8640
#define SMEM_FLOATS 28440
#define SMEM_BYTES  (SMEM_FLOATS * 4)   // 113760 B -> 2 CTAs/SM (228KB carveout)

__device__ float g_bm[MAXN];

typedef unsigned long long u64;

// ---------------- f32x2 helpers (sm_100+ packed fp32) ----------------
__device__ __forceinline__ u64 splat2(float a) {
    u64 r; asm("mov.b64 %0, {%1, %1};" : "=l"(r) : "f"(a)); return r;
}
__device__ __forceinline__ u64 fma2(u64 a, u64 b, u64 c) {
    u64 d; asm("fma.rn.f32x2 %0, %1, %2, %3;" : "=l"(d) : "l"(a), "l"(b), "l"(c)); return d;
}
__device__ __forceinline__ void unpk(u64 v, float& x, float& y) {
    asm("mov.b64 {%0, %1}, %2;" : "=f"(x), "=f"(y) : "l"(v));
}

__device__ __forceinline__ float elu1(float x) {
    float e = __expf(x) - 1.0f;
    return x > 0.0f ? x : e;
}

__global__ __launch_bounds__(NTHREADS, 2)
void cnn_kernel(const float* __restrict__ uu,
                const float* __restrict__ w1, const float* __restrict__ b1,
                const float* __restrict__ w2, const float* __restrict__ b2,
                const float* __restrict__ w3, const float* __restrict__ b3,
                const float* __restrict__ w4, const float* __restrict__ b4,
                const float* __restrict__ w5, const float* __restrict__ b5,
                const float* __restrict__ w6, const float* __restrict__ b6,
                int N)
{
    extern __shared__ float s[];
    const int tid = threadIdx.x;
    const int g0  = blockIdx.x * T;

    // ---- load + transpose weights ----
    for (int i = tid; i < 100; i += NTHREADS) {           // w1 (20,1,5)
        int co = i / 5, t = i % 5;
        s[OW1 + t * 20 + co] = w1[i];
    }
    for (int i = tid; i < 20; i += NTHREADS)  s[OB1 + i] = b1[i];
    for (int i = tid; i < 4000; i += NTHREADS) {          // w2 (40,20,5)
        int co = i / 100, r = i % 100, ci = r / 5, t = r % 5;
        s[OW2 + (ci * 5 + t) * 40 + co] = w2[i];
    }
    for (int i = tid; i < 40; i += NTHREADS)  s[OB2 + i] = b2[i];
    for (int i = tid; i < 3200; i += NTHREADS) {          // w3 (80,40,1)
        int co = i / 40, ci = i % 40;
        s[OW3 + ci * 80 + co] = w3[i];
    }
    for (int i = tid; i < 80; i += NTHREADS)  s[OB3 + i] = b3[i];
    for (int i = tid; i < 3200; i += NTHREADS) {          // w4 (40,80,1)
        int co = i / 80, ci = i % 80;
        s[OW4 + ci * 40 + co] = w4[i];
    }
    for (int i = tid; i < 40; i += NTHREADS)  s[OB4 + i] = b4[i];
    for (int i = tid; i < 2400; i += NTHREADS) {          // w5 (20,40,3)
        int co = i / 120, r = i % 120, ci = r / 3, t = r % 3;
        s[OW5 + (ci * 3 + t) * 20 + co] = w5[i];
    }
    for (int i = tid; i < 20; i += NTHREADS)  s[OB5 + i] = b5[i];
    for (int i = tid; i < 20; i += NTHREADS)  s[OW6 + i] = w6[i];
    if (tid == 0) s[OB6] = b6[0];

    // ---- dif = avg_diff(uu), window [g0-5, g0+105): 110 real, padded to 118 ----
    for (int ld = tid; ld < 118; ld += NTHREADS) {
        int gd = g0 - 5 + ld;
        float v = 0.0f;
        if (ld < 110 && gd >= 0 && gd < N) {
            if (gd == 0)            v = __ldg(&uu[1]) - __ldg(&uu[0]);
            else if (gd == N - 1)   v = __ldg(&uu[N - 1]) - __ldg(&uu[N - 2]);
            else                    v = 0.5f * (__ldg(&uu[gd + 1]) - __ldg(&uu[gd - 1]));
        }
        s[ODIF + ld] = v;
    }
    __syncthreads();

    // ---- layer 1: 1 -> 20, k=5, pad 2. y1[lp] at gp = g0-3+lp, real lp<106 ----
    // 2240 items fill entire 20x112 region (zeros beyond real range).
    for (int item = tid; item < 20 * 112; item += NTHREADS) {
        int co = item / 112, lp = item % 112;
        float acc = s[OB1 + co];
        #pragma unroll
        for (int t = 0; t < 5; t++)
            acc += s[OW1 + t * 20 + co] * s[ODIF + lp + t];
        int gp = g0 - 3 + lp;
        float v = elu1(acc);
        if (lp >= 106 || gp < 0 || gp >= N) v = 0.0f;
        s[OY1 + co * S1 + lp] = v;
    }
    __syncthreads();

    // ---- layer 2: 20 -> 40, k=5, pad 2. y2[lp] at gp = g0-1+lp, real lp<102 ----
    // 240 items: 20 ch-pairs x 12 posgroups (P_T=9, covers 108)
    if (tid < 240) {
        const int cog = tid / 12, posg = tid % 12;
        const int co0 = cog * 2, lp0 = posg * 9;
        u64 acc[9];
        {
            u64 bp = *reinterpret_cast<const u64*>(&s[OB2 + co0]);
            #pragma unroll
            for (int p = 0; p < 9; p++) acc[p] = bp;
        }
        for (int ci = 0; ci < 20; ci++) {
            const float* yr = &s[OY1 + ci * S1 + lp0];
            const float* wp = &s[OW2 + ci * 5 * 40 + co0];
            u64 as[13];
            #pragma unroll
            for (int j = 0; j < 13; j++) as[j] = splat2(yr[j]);
            #pragma unroll
            for (int t = 0; t < 5; t++) {
                u64 w = *reinterpret_cast<const u64*>(&wp[t * 40]);
                #pragma unroll
                for (int p = 0; p < 9; p++)
                    acc[p] = fma2(w, as[t + p], acc[p]);
            }
        }
        #pragma unroll
        for (int p = 0; p < 9; p++) {
            int lp = lp0 + p, gp = g0 - 1 + lp;
            bool kill = (lp >= 102) | (gp < 0) | (gp >= N);
            float x, y; unpk(acc[p], x, y);
            float v0 = elu1(x), v1 = elu1(y);
            if (kill) { v0 = 0.0f; v1 = 0.0f; }
            s[OY2 + co0 * S2 + lp] = v0;
            s[OY2 + (co0 + 1) * S2 + lp] = v1;
        }
    }
    __syncthreads();

    // ---- layer 3: 40 -> 80, k=1. 255 items: 5 cog (8 ch-pairs) x 51 posg (P_T=2) ----
    if (tid < 255) {
        const int cog = tid / 51, posg = tid % 51;
        const int co0 = cog * 16, lp0 = posg * 2;
        u64 acc[8][2];
        #pragma unroll
        for (int c = 0; c < 8; c++) {
            u64 bp = *reinterpret_cast<const u64*>(&s[OB3 + co0 + 2 * c]);
            acc[c][0] = bp; acc[c][1] = bp;
        }
        for (int ci = 0; ci < 40; ci++) {
            const float* yr = &s[OY2 + ci * S2 + lp0];
            u64 a0 = splat2(yr[0]), a1 = splat2(yr[1]);
            const u64* wp = reinterpret_cast<const u64*>(&s[OW3 + ci * 80 + co0]);
            #pragma unroll
            for (int c = 0; c < 8; c++) {
                u64 w = wp[c];
                acc[c][0] = fma2(w, a0, acc[c][0]);
                acc[c][1] = fma2(w, a1, acc[c][1]);
            }
        }
        #pragma unroll
        for (int c = 0; c < 8; c++)
            #pragma unroll
            for (int p = 0; p < 2; p++) {
                int lp = lp0 + p, gp = g0 - 1 + lp;
                bool kill = (lp >= 102) | (gp < 0) | (gp >= N);
                float x, y; unpk(acc[c][p], x, y);
                float v0 = elu1(x), v1 = elu1(y);
                if (kill) { v0 = 0.0f; v1 = 0.0f; }
                s[OY3 + (co0 + 2 * c) * S2 + lp] = v0;
                s[OY3 + (co0 + 2 * c + 1) * S2 + lp] = v1;
            }
    }
    __syncthreads();

    // ---- layer 4: 80 -> 40, k=1. 255 items: 5 cog (4 ch-pairs) x 51 posg (P_T=2) ----
    // writes y4 into the (dead) y2 region
    if (tid < 255) {
        const int cog = tid / 51, posg = tid % 51;
        const int co0 = cog * 8, lp0 = posg * 2;
        u64 acc[4][2];
        #pragma unroll
        for (int c = 0; c < 4; c++) {
            u64 bp = *reinterpret_cast<const u64*>(&s[OB4 + co0 + 2 * c]);
            acc[c][0] = bp; acc[c][1] = bp;
        }
        for (int ci = 0; ci < 80; ci++) {
            const float* yr = &s[OY3 + ci * S2 + lp0];
            u64 a0 = splat2(yr[0]), a1 = splat2(yr[1]);
            const u64* wp = reinterpret_cast<const u64*>(&s[OW4 + ci * 40 + co0]);
            #pragma unroll
            for (int c = 0; c < 4; c++) {
                u64 w = wp[c];
                acc[c][0] = fma2(w, a0, acc[c][0]);
                acc[c][1] = fma2(w, a1, acc[c][1]);
            }
        }
        #pragma unroll
        for (int c = 0; c < 4; c++)
            #pragma unroll
            for (int p = 0; p < 2; p++) {
                int lp = lp0 + p, gp = g0 - 1 + lp;
                bool kill = (lp >= 102) | (gp < 0) | (gp >= N);
                float x, y; unpk(acc[c][p], x, y);
                float v0 = elu1(x), v1 = elu1(y);
                if (kill) { v0 = 0.0f; v1 = 0.0f; }
                s[OY2 + (co0 + 2 * c) * S2 + lp] = v0;
                s[OY2 + (co0 + 2 * c + 1) * S2 + lp] = v1;
            }
    }
    __syncthreads();

    // ---- layer 5: 40 -> 20, k=3, pad 1. y5[lp] at gp = g0+lp, real lp<100 ----
    // 255 items: 5 cog (2 ch-pairs) x 51 posg (P_T=2). Reads y4 (OY2), writes y5 (OY1).
    if (tid < 255) {
        const int cog = tid / 51, posg = tid % 51;
        const int co0 = cog * 4, lp0 = posg * 2;
        u64 acc[2][2];
        #pragma unroll
        for (int c = 0; c < 2; c++) {
            u64 bp = *reinterpret_cast<const u64*>(&s[OB5 + co0 + 2 * c]);
            acc[c][0] = bp; acc[c][1] = bp;
        }
        for (int ci = 0; ci < 40; ci++) {
            const float* yr = &s[OY2 + ci * S2 + lp0];
            const float* wp = &s[OW5 + ci * 3 * 20 + co0];
            u64 as[4];
            #pragma unroll
            for (int j = 0; j < 4; j++) as[j] = splat2(yr[j]);
            #pragma unroll
            for (int t = 0; t < 3; t++) {
                u64 w0 = *reinterpret_cast<const u64*>(&wp[t * 20]);
                u64 w1 = *reinterpret_cast<const u64*>(&wp[t * 20 + 2]);
                #pragma unroll
                for (int p = 0; p < 2; p++) {
                    acc[0][p] = fma2(w0, as[t + p], acc[0][p]);
                    acc[1][p] = fma2(w1, as[t + p], acc[1][p]);
                }
            }
        }
        #pragma unroll
        for (int c = 0; c < 2; c++)
            #pragma unroll
            for (int p = 0; p < 2; p++) {
                int lp = lp0 + p, gp = g0 + lp;
                bool kill = (lp >= 100) | (gp >= N);
                float x, y; unpk(acc[c][p], x, y);
                float v0 = elu1(x), v1 = elu1(y);
                if (kill) { v0 = 0.0f; v1 = 0.0f; }
                s[OY1 + (co0 + 2 * c) * S1 + lp] = v0;
                s[OY1 + (co0 + 2 * c + 1) * S1 + lp] = v1;
            }
    }
    __syncthreads();

    // ---- layer 6: 20 -> 1, k=1, sigmoid, + 0.1 ----
    for (int lp = tid; lp < T; lp += NTHREADS) {
        int gp = g0 + lp;
        if (gp < N) {
            float acc = s[OB6];
            #pragma unroll
            for (int c = 0; c < 20; c++)
                acc += s[OW6 + c] * s[OY1 + c * S1 + lp];
            float sg = 1.0f / (1.0f + __expf(-acc));
            g_bm[gp] = sg + 0.1f;
        }
    }
}

// ---------------- WENO reconstruction ----------------
__device__ __forceinline__ float weno_flux(float a, float b, float c, float d, float e,
                                           float bm_m1, float bm_0, float bm_p1)
{
    const float C1312 = 13.0f / 12.0f;
    const float E = 1e-13f;
    float f0 = (11.0f * c - 7.0f * d + 2.0f * e) * (1.0f / 6.0f);
    float f1 = (2.0f * b + 5.0f * c - d) * (1.0f / 6.0f);
    float f2 = (-a + 5.0f * b + 2.0f * c) * (1.0f / 6.0f);

    float t0a = c - 2.0f * d + e, t0b = 3.0f * c - 4.0f * d + e;
    float t1a = b - 2.0f * c + d, t1b = b - d;
    float t2a = a - 2.0f * b + c, t2b = a - 4.0f * b + 3.0f * c;
    float b0 = C1312 * t0a * t0a + 0.25f * t0b * t0b;
    float b1 = C1312 * t1a * t1a + 0.25f * t1b * t1b;
    float b2 = C1312 * t2a * t2a + 0.25f * t2b * t2b;

    b0 *= bm_p1;
    b1 *= bm_0;
    b2 *= bm_m1;

    float brs = (b2 - b0) * (b2 - b0);
    float e0 = (E + b0) * (E + b0);
    float e1 = (E + b1) * (E + b1);
    float e2 = (E + b2) * (E + b2);
    float om0 = 0.1f / e0 * (brs + e0);
    float om1 = 0.6f / e1 * (brs + e1);
    float om2 = 0.3f / e2 * (brs + e2);
    return (om0 * f0 + om1 * f1 + om2 * f2) / (om0 + om1 + om2);
}

__global__ void weno_kernel(const float* __restrict__ uu, float* __restrict__ out, int N)
{
    int i = blockIdx.x * blockDim.x + threadIdx.x;
    if (i >= N) return;
    int im2 = i - 2, im1 = i - 1, ip1 = i + 1, ip2 = i + 2, ip3 = i + 3;
    if (im2 < 0) im2 += N;
    if (im1 < 0) im1 += N;
    if (ip1 >= N) ip1 -= N;
    if (ip2 >= N) ip2 -= N;
    if (ip3 >= N) ip3 -= N;

    float umm = __ldg(&uu[im2]), um = __ldg(&uu[im1]), u0 = __ldg(&uu[i]);
    float up  = __ldg(&uu[ip1]), upp = __ldg(&uu[ip2]), uppp = __ldg(&uu[ip3]);
    float bm_m1 = g_bm[im1], bm_0 = g_bm[i], bm_p1 = g_bm[ip1];

    float fluxp = weno_flux(um, u0, up, upp, uppp, bm_m1, bm_0, bm_p1);
    float fluxn = weno_flux(umm, um, u0, up, upp, bm_m1, bm_0, bm_p1);

    out[i] = fluxp - fluxn;
}

extern "C" void kernel_launch(void* const* d_in, const int* in_sizes, int n_in,
                              void* d_out, int out_size)
{
    const float* uu = (const float*)d_in[0];
    const float* w1 = (const float*)d_in[1];
    const float* b1 = (const float*)d_in[2];
    const float* w2 = (const float*)d_in[3];
    const float* b2 = (const float*)d_in[4];
    const float* w3 = (const float*)d_in[5];
    const float* b3 = (const float*)d_in[6];
    const float* w4 = (const float*)d_in[7];
    const float* b4 = (const float*)d_in[8];
    const float* w5 = (const float*)d_in[9];
    const float* b5 = (const float*)d_in[10];
    const float* w6 = (const float*)d_in[11];
    const float* b6 = (const float*)d_in[12];
    float* out = (float*)d_out;
    int N = in_sizes[0];

    cudaFuncSetAttribute(cnn_kernel, cudaFuncAttributeMaxDynamicSharedMemorySize, SMEM_BYTES);

    int nb = (N + T - 1) / T;
    cnn_kernel<<<nb, NTHREADS, SMEM_BYTES>>>(uu, w1, b1, w2, b2, w3, b3, w4, b4,
                                             w5, b5, w6, b6, N);
    weno_kernel<<<(N + 255) / 256, 256>>>(uu, out, N);
}